// round 11
// baseline (speedup 1.0000x reference)
#include <cuda_runtime.h>
#include <cuda_bf16.h>
#include <mma.h>
#include <math.h>
#include <cstdint>

using namespace nvcuda;

constexpr int S_ = 1024;
constexpr int B_ = 32;
constexpr int E_ = 1024;
constexpr int P_ = 128;
constexpr int NQK = 2 * P_;   // 256

__device__ float g_qk[(size_t)B_ * S_ * NQK];
__device__ __nv_bfloat16 g_Wb[(size_t)NQK * E_];
__device__ float g_fwd[B_ * S_];
__device__ float g_bwd[B_ * S_];
__device__ float g_csp[B_ * S_];
__device__ float g_f[B_ * S_];

__device__ __forceinline__ uint32_t smem_u32(const void* p) {
    uint32_t a;
    asm("{ .reg .u64 t; cvta.to.shared.u64 t, %1; cvt.u32.u64 %0, t; }"
        : "=r"(a) : "l"(p));
    return a;
}
#define CP_ASYNC16(dst_u32, src_ptr) \
    asm volatile("cp.async.cg.shared.global [%0], [%1], 16;" \
                 :: "r"(dst_u32), "l"(src_ptr))
#define CP_COMMIT() asm volatile("cp.async.commit_group;" ::: "memory")
#define CP_WAIT1()  asm volatile("cp.async.wait_group 1;" ::: "memory")

// ---------------------------------------------------------------------------
// Stage 0: convert W (fp32 [256,1024]) to bf16 once.
// ---------------------------------------------------------------------------
__global__ __launch_bounds__(256) void conv_w(const float* __restrict__ W)
{
    int i = blockIdx.x * 256 + threadIdx.x;
    float4 v = ((const float4*)W)[i];
    __nv_bfloat162 p0 = __floats2bfloat162_rn(v.x, v.y);
    __nv_bfloat162 p1 = __floats2bfloat162_rn(v.z, v.w);
    *(uint2*)&g_Wb[(size_t)i * 4] = make_uint2(*(unsigned*)&p0, *(unsigned*)&p1);
}

// ---------------------------------------------------------------------------
// Stage 1: GEMM qk = ctx @ W^T. M=32768, N=256, K=1024.
// bf16 wmma m16n16k16. BM=64, BN=256, BK=32 per pipeline step (32 barriers).
// B: 3-stage cp.async ring from g_Wb. A: 2-stage LDG->cvt->STS.
// ---------------------------------------------------------------------------
constexpr int GBM = 64;
constexpr int GBK = 32;
constexpr int GLD = 40;                 // bf16 per smem row (80B), conflict-free
constexpr int A_ST = GBM * GLD;         // 2560 elems / stage
constexpr int B_ST = NQK * GLD;         // 10240 elems / stage
constexpr int NSLAB = E_ / GBK;         // 32
constexpr int GEMM_SMEM = (2 * A_ST + 3 * B_ST) * 2;   // 71680 B

__global__ __launch_bounds__(256, 2) void gemm_qk(const float* __restrict__ ctx)
{
    extern __shared__ __align__(16) char dsm[];
    __nv_bfloat16* As = (__nv_bfloat16*)dsm;             // [2][64][40]
    __nv_bfloat16* Bs = (__nv_bfloat16*)dsm + 2 * A_ST;  // [3][256][40]

    const int m0 = blockIdx.x * GBM;
    const int tid = threadIdx.x;
    const int warp = tid >> 5;
    const int wr = warp & 1;
    const int wc = warp >> 1;

    const uint32_t bs_base = smem_u32(Bs);

    wmma::fragment<wmma::accumulator, 16, 16, 16, float> acc[2][4];
#pragma unroll
    for (int i = 0; i < 2; i++)
#pragma unroll
        for (int j = 0; j < 4; j++)
            wmma::fill_fragment(acc[i][j], 0.0f);

    // B slab: 256 rows x 32 bf16 (64B = 4 granules), row = tid, granule = it
    auto cpB = [&](int t, int buf) {
        const __nv_bfloat16* srow = g_Wb + (size_t)tid * E_ + t * GBK;
        uint32_t drow = bs_base + (buf * B_ST + tid * GLD) * 2;
#pragma unroll
        for (int it = 0; it < 4; it++)
            CP_ASYNC16(drow + it * 16, srow + it * 8);
    };

    // A slab: 64 rows x 32 fp32 = 512 float4, 2/thread
    float4 ra[2];
    auto ldgA = [&](int t) {
#pragma unroll
        for (int it = 0; it < 2; it++) {
            int g = it * 256 + tid;
            int r = g >> 3, c4 = (g & 7) * 4;
            ra[it] = *(const float4*)(ctx + (size_t)(m0 + r) * E_ + t * GBK + c4);
        }
    };
    auto stsA = [&](int buf) {
#pragma unroll
        for (int it = 0; it < 2; it++) {
            int g = it * 256 + tid;
            int r = g >> 3, c4 = (g & 7) * 4;
            __nv_bfloat162 p0 = __floats2bfloat162_rn(ra[it].x, ra[it].y);
            __nv_bfloat162 p1 = __floats2bfloat162_rn(ra[it].z, ra[it].w);
            *(uint2*)&As[buf * A_ST + r * GLD + c4] =
                make_uint2(*(unsigned*)&p0, *(unsigned*)&p1);
        }
    };

    // prologue
    cpB(0, 0); CP_COMMIT();
    cpB(1, 1); CP_COMMIT();
    ldgA(0);
    stsA(0);
    ldgA(1);
    CP_WAIT1();            // B(0) landed
    __syncthreads();

    for (int t = 0; t < NSLAB; t++) {
        if (t + 2 < NSLAB) cpB(t + 2, (t + 2) % 3);
        CP_COMMIT();       // uniform wait depth

        const __nv_bfloat16* ab = As + (t & 1) * A_ST + (wr * 32) * GLD;
        const __nv_bfloat16* bb = Bs + (t % 3) * B_ST + (wc * 64) * GLD;
#pragma unroll
        for (int kk = 0; kk < GBK; kk += 16) {
            wmma::fragment<wmma::matrix_a, 16, 16, 16, __nv_bfloat16, wmma::row_major> af[2];
            wmma::fragment<wmma::matrix_b, 16, 16, 16, __nv_bfloat16, wmma::col_major> bf[4];
#pragma unroll
            for (int i = 0; i < 2; i++)
                wmma::load_matrix_sync(af[i], ab + (i * 16) * GLD + kk, GLD);
#pragma unroll
            for (int j = 0; j < 4; j++)
                wmma::load_matrix_sync(bf[j], bb + (j * 16) * GLD + kk, GLD);
#pragma unroll
            for (int i = 0; i < 2; i++)
#pragma unroll
                for (int j = 0; j < 4; j++)
                    wmma::mma_sync(acc[i][j], af[i], bf[j], acc[i][j]);
        }

        if (t + 1 < NSLAB) {
            stsA((t + 1) & 1);
            if (t + 2 < NSLAB) ldgA(t + 2);
            CP_WAIT1();    // B(t+1) landed
            __syncthreads();
        }
    }

#pragma unroll
    for (int i = 0; i < 2; i++)
#pragma unroll
        for (int j = 0; j < 4; j++) {
            float* dst = g_qk + (size_t)(m0 + wr * 32 + i * 16) * NQK
                              + wc * 64 + j * 16;
            wmma::store_matrix_sync(dst, acc[i][j], NQK, wmma::mem_row_major);
        }
}

// ---------------------------------------------------------------------------
// Stage 2: neighbor scores, one warp per (s,b). Coalesced float4.
// ---------------------------------------------------------------------------
__global__ __launch_bounds__(256) void scores(const float* __restrict__ bias)
{
    const int warp = threadIdx.x >> 5;
    const int lane = threadIdx.x & 31;
    const int m = blockIdx.x * 8 + warp;      // m = s*B + b
    const int s = m >> 5;
    const int b = m & 31;
    if (s >= S_ - 1) return;

    const float* r0 = g_qk + (size_t)m * NQK;
    const float* r1 = r0 + (size_t)B_ * NQK;

    float4 q0 = *(const float4*)(r0 + lane * 4);
    float4 k0 = *(const float4*)(r0 + P_ + lane * 4);
    float4 q1 = *(const float4*)(r1 + lane * 4);
    float4 k1 = *(const float4*)(r1 + P_ + lane * 4);
    float4 bq = *(const float4*)(bias + lane * 4);
    float4 bk = *(const float4*)(bias + P_ + lane * 4);

    q0.x += bq.x; q0.y += bq.y; q0.z += bq.z; q0.w += bq.w;
    q1.x += bq.x; q1.y += bq.y; q1.z += bq.z; q1.w += bq.w;
    k0.x += bk.x; k0.y += bk.y; k0.z += bk.z; k0.w += bk.w;
    k1.x += bk.x; k1.y += bk.y; k1.z += bk.z; k1.w += bk.w;

    float tf = q0.x * k1.x + q0.y * k1.y + q0.z * k1.z + q0.w * k1.w;
    float tb = q1.x * k0.x + q1.y * k0.y + q1.z * k0.z + q1.w * k0.w;

#pragma unroll
    for (int o = 16; o > 0; o >>= 1) {
        tf += __shfl_down_sync(0xffffffffu, tf, o);
        tb += __shfl_down_sync(0xffffffffu, tb, o);
    }
    if (lane == 0) {
        g_fwd[b * S_ + s] = tf * (1.0f / (float)E_);
        g_bwd[b * S_ + s] = tb * (1.0f / (float)E_);
    }
}

// ---------------------------------------------------------------------------
// Stage 3: softmax/roll/log + exclusive scan; stores f = exp(log_prob).
// ---------------------------------------------------------------------------
__global__ __launch_bounds__(1024) void rowscan(const float* __restrict__ prior,
                                                const int* __restrict__ mask,
                                                float* __restrict__ out_na)
{
    const int b = blockIdx.x;
    const int s = threadIdx.x;

    __shared__ float s_prob1[S_];
    __shared__ float s_warp[32];

    const int rm = mask[b * S_ + ((s + 1) & (S_ - 1))];

    float c0 = (s < S_ - 1) ? g_fwd[b * S_ + s] : -INFINITY;
    if (rm == 1) c0 = -INFINITY;
    float c1 = (s > 0) ? g_bwd[b * S_ + s - 1] : -INFINITY;

    float mx = fmaxf(c0, c1);
    float e0 = __expf(c0 - mx);
    float e1 = __expf(c1 - mx);
    float inv = 1.0f / (e0 + e1);
    float p0 = e0 * inv;
    float p1 = e1 * inv;

    s_prob1[s] = p1;
    __syncthreads();

    float shift = (s < S_ - 1) ? s_prob1[s + 1] : 0.0f;

    float pv = sqrtf(p0 * shift + 1e-6f);
    float pr = prior[b * S_ + s];
    float na = pr + (1.0f - pr) * pv;
    out_na[b * S_ + s] = na;

    float lp = logf(na);
    float fv = na;
    if (rm == 1) { lp = 0.0f; fv = 1.0f; }
    g_f[b * S_ + s] = fv;

    float v = lp;
    const unsigned lane = s & 31;
#pragma unroll
    for (int o = 1; o < 32; o <<= 1) {
        float n = __shfl_up_sync(0xffffffffu, v, o);
        if (lane >= (unsigned)o) v += n;
    }
    if (lane == 31) s_warp[s >> 5] = v;
    __syncthreads();
    if (s < 32) {
        float w = s_warp[s];
#pragma unroll
        for (int o = 1; o < 32; o <<= 1) {
            float n = __shfl_up_sync(0xffffffffu, w, o);
            if (s >= o) w += n;
        }
        s_warp[s] = w;
    }
    __syncthreads();
    float incl = v + ((s >= 32) ? s_warp[(s >> 5) - 1] : 0.0f);
    g_csp[b * S_ + s] = incl - lp;
}

// ---------------------------------------------------------------------------
// Stage 4: constituent[b][i][j]. 512 threads, 32 rows/block, min 3 blocks/SM.
// ---------------------------------------------------------------------------
constexpr int RPB = 32;

__global__ __launch_bounds__(512, 3) void outerk(float* __restrict__ out)
{
    const int b  = blockIdx.y;
    const int i0 = blockIdx.x * RPB;
    const int tid = threadIdx.x;

    __shared__ float sc[S_];
    __shared__ float sf[S_];
    if (tid < 256)
        ((float4*)sc)[tid] = ((const float4*)(g_csp + b * S_))[tid];
    else
        ((float4*)sf)[tid - 256] = ((const float4*)(g_f + b * S_))[tid - 256];
    __syncthreads();

    const int rsub = tid >> 7;            // 0..3
    const int j0 = (tid & 127) * 8;

    float4 f0 = *(const float4*)&sf[j0];
    float4 f1 = *(const float4*)&sf[j0 + 4];
    float4 c0 = *(const float4*)&sc[j0];
    float4 c1 = *(const float4*)&sc[j0 + 4];

#pragma unroll 4
    for (int sweep = 0; sweep < RPB / 4; sweep++) {
        const int i = i0 + sweep * 4 + rsub;
        const float ci = sc[i];

        float r[8];
        if (j0 + 7 < i) {
            float v = __expf(ci - c0.w);
            r[3] = v;
            v *= f0.z; r[2] = v;
            v *= f0.y; r[1] = v;
            v *= f0.x; r[0] = v;
            float w = __expf(ci - c1.w);
            r[7] = w;
            w *= f1.z; r[6] = w;
            w *= f1.y; r[5] = w;
            w *= f1.x; r[4] = w;
        } else if (j0 > i) {
            float v = __expf(c0.x - ci);
            r[0] = v;
            v *= f0.x; r[1] = v;
            v *= f0.y; r[2] = v;
            v *= f0.z; r[3] = v;
            float w = __expf(c1.x - ci);
            r[4] = w;
            w *= f1.x; r[5] = w;
            w *= f1.y; r[6] = w;
            w *= f1.z; r[7] = w;
        } else {
            const float cj[8] = {c0.x, c0.y, c0.z, c0.w, c1.x, c1.y, c1.z, c1.w};
#pragma unroll
            for (int l = 0; l < 8; l++) {
                int j = j0 + l;
                float d = (j > i) ? (cj[l] - ci) : (ci - cj[l]);
                r[l] = (j == i) ? 0.0f : __expf(d);
            }
        }

        float* dst = out + ((size_t)b * S_ + i) * S_ + j0;
        __stcs((float4*)dst,       make_float4(r[0], r[1], r[2], r[3]));
        __stcs((float4*)(dst + 4), make_float4(r[4], r[5], r[6], r[7]));
    }
}

// ---------------------------------------------------------------------------
extern "C" void kernel_launch(void* const* d_in, const int* in_sizes, int n_in,
                              void* d_out, int out_size)
{
    const float* ctx   = (const float*)d_in[0];
    const float* prior = (const float*)d_in[1];
    const int*   mask  = (const int*)d_in[2];
    const float* W     = (const float*)d_in[3];
    const float* bias  = (const float*)d_in[4];

    float* out_c  = (float*)d_out;
    float* out_na = (float*)d_out + (size_t)B_ * S_ * S_;

    cudaFuncSetAttribute(gemm_qk, cudaFuncAttributeMaxDynamicSharedMemorySize,
                         GEMM_SMEM);

    conv_w<<<256, 256>>>(W);

    gemm_qk<<<(B_ * S_) / GBM, 256, GEMM_SMEM>>>(ctx);

    scores<<<(B_ * S_) / 8, 256>>>(bias);

    rowscan<<<B_, S_>>>(prior, mask, out_na);

    dim3 g4(S_ / RPB, B_);
    outerk<<<g4, 512>>>(out_c);
}

// round 12
// speedup vs baseline: 1.0656x; 1.0656x over previous
#include <cuda_runtime.h>
#include <cuda_bf16.h>
#include <mma.h>
#include <math.h>
#include <cstdint>

using namespace nvcuda;

constexpr int S_ = 1024;
constexpr int B_ = 32;
constexpr int E_ = 1024;
constexpr int P_ = 128;
constexpr int NQK = 2 * P_;   // 256

__device__ __nv_bfloat16 g_qk[(size_t)B_ * S_ * NQK];
__device__ __nv_bfloat16 g_Wb[(size_t)NQK * E_];
__device__ float g_fwd[B_ * S_];
__device__ float g_bwd[B_ * S_];
__device__ float g_csp[B_ * S_];
__device__ float g_f[B_ * S_];

__device__ __forceinline__ uint32_t smem_u32(const void* p) {
    uint32_t a;
    asm("{ .reg .u64 t; cvta.to.shared.u64 t, %1; cvt.u32.u64 %0, t; }"
        : "=r"(a) : "l"(p));
    return a;
}
#define CP_ASYNC16(dst_u32, src_ptr) \
    asm volatile("cp.async.cg.shared.global [%0], [%1], 16;" \
                 :: "r"(dst_u32), "l"(src_ptr))
#define CP_COMMIT() asm volatile("cp.async.commit_group;" ::: "memory")
#define CP_WAIT1()  asm volatile("cp.async.wait_group 1;" ::: "memory")

// ---------------------------------------------------------------------------
// Stage 0: convert W (fp32 [256,1024]) to bf16 once.
// ---------------------------------------------------------------------------
__global__ __launch_bounds__(256) void conv_w(const float* __restrict__ W)
{
    int i = blockIdx.x * 256 + threadIdx.x;
    float4 v = ((const float4*)W)[i];
    __nv_bfloat162 p0 = __floats2bfloat162_rn(v.x, v.y);
    __nv_bfloat162 p1 = __floats2bfloat162_rn(v.z, v.w);
    *(uint2*)&g_Wb[(size_t)i * 4] = make_uint2(*(unsigned*)&p0, *(unsigned*)&p1);
}

// ---------------------------------------------------------------------------
// Stage 1: GEMM qk = ctx @ W^T. M=32768, N=256, K=1024.
// bf16 wmma m16n16k16. BM=64, BN=256, BK=16; 256 threads (8 warps 2x4).
// B: 3-stage cp.async ring from g_Wb. A: 2-stage LDG->cvt->STS.
// bf16 output via per-warp smem staging.
// ---------------------------------------------------------------------------
constexpr int GBM = 64;
constexpr int GBK = 16;
constexpr int GLD = 24;                 // bf16 per smem row (48B)
constexpr int A_ST = GBM * GLD;
constexpr int B_ST = NQK * GLD;
constexpr int NSLAB = E_ / GBK;         // 64

__global__ __launch_bounds__(256, 2) void gemm_qk(const float* __restrict__ ctx)
{
    __shared__ __nv_bfloat16 As[2][GBM][GLD];
    __shared__ __nv_bfloat16 Bs[3][NQK][GLD];
    __shared__ float epi[8][16 * 24];

    const int m0 = blockIdx.x * GBM;
    const int tid = threadIdx.x;
    const int warp = tid >> 5;
    const int lane = tid & 31;
    const int wr = warp & 1;
    const int wc = warp >> 1;

    const int lr = tid >> 2;          // A row 0..63
    const int lc = (tid & 3) * 4;     // A col start

    const int br0 = tid >> 1;         // B cp.async row base (0..127)
    const int bh0 = tid & 1;
    const uint32_t bs_base = smem_u32(&Bs[0][0][0]);

    wmma::fragment<wmma::accumulator, 16, 16, 16, float> acc[2][4];
#pragma unroll
    for (int i = 0; i < 2; i++)
#pragma unroll
        for (int j = 0; j < 4; j++)
            wmma::fill_fragment(acc[i][j], 0.0f);

    auto cpB = [&](int t, int buf) {
#pragma unroll
        for (int it = 0; it < 2; it++) {
            int row = br0 + it * 128;
            const __nv_bfloat16* src = g_Wb + (size_t)row * E_ + t * GBK + bh0 * 8;
            uint32_t dst = bs_base + buf * (B_ST * 2) + row * 48 + bh0 * 16;
            CP_ASYNC16(dst, src);
        }
    };

    float4 ra;
    auto ldgA = [&](int t) {
        ra = *(const float4*)(ctx + (size_t)(m0 + lr) * E_ + t * GBK + lc);
    };
    auto stsA = [&](int buf) {
        __nv_bfloat162 a01 = __floats2bfloat162_rn(ra.x, ra.y);
        __nv_bfloat162 a23 = __floats2bfloat162_rn(ra.z, ra.w);
        *(uint2*)(uintptr_t)(&As[buf][lr][lc]) =
            make_uint2(*(unsigned*)&a01, *(unsigned*)&a23);
    };

    // prologue
    cpB(0, 0); CP_COMMIT();
    cpB(1, 1); CP_COMMIT();
    ldgA(0);
    stsA(0);
    ldgA(1);
    CP_WAIT1();
    __syncthreads();

    for (int t = 0; t < NSLAB; t++) {
        if (t + 2 < NSLAB) cpB(t + 2, (t + 2) % 3);
        CP_COMMIT();

        const int ab = t & 1;
        const int bb = t % 3;
        wmma::fragment<wmma::matrix_a, 16, 16, 16, __nv_bfloat16, wmma::row_major> af[2];
        wmma::fragment<wmma::matrix_b, 16, 16, 16, __nv_bfloat16, wmma::col_major> bf[4];
#pragma unroll
        for (int i = 0; i < 2; i++)
            wmma::load_matrix_sync(af[i], &As[ab][wr * 32 + i * 16][0], GLD);
#pragma unroll
        for (int j = 0; j < 4; j++)
            wmma::load_matrix_sync(bf[j], &Bs[bb][wc * 64 + j * 16][0], GLD);
#pragma unroll
        for (int i = 0; i < 2; i++)
#pragma unroll
            for (int j = 0; j < 4; j++)
                wmma::mma_sync(acc[i][j], af[i], bf[j], acc[i][j]);

        if (t + 1 < NSLAB) {
            stsA((t + 1) & 1);
            if (t + 2 < NSLAB) ldgA(t + 2);
            CP_WAIT1();
            __syncthreads();
        }
    }

    // ---- epilogue: stage fp32 fragments through smem, emit packed bf16 ----
    float* ebuf = epi[warp];
    const int er = lane >> 1;           // 0..15
    const int ec = (lane & 1) * 8;      // 0 or 8
#pragma unroll
    for (int i = 0; i < 2; i++)
#pragma unroll
        for (int j = 0; j < 4; j++) {
            wmma::store_matrix_sync(ebuf, acc[i][j], 24, wmma::mem_row_major);
            __syncwarp();
            const float* p = ebuf + er * 24 + ec;
            __nv_bfloat162 h0 = __floats2bfloat162_rn(p[0], p[1]);
            __nv_bfloat162 h1 = __floats2bfloat162_rn(p[2], p[3]);
            __nv_bfloat162 h2 = __floats2bfloat162_rn(p[4], p[5]);
            __nv_bfloat162 h3 = __floats2bfloat162_rn(p[6], p[7]);
            size_t row = m0 + wr * 32 + i * 16 + er;
            *(uint4*)(g_qk + row * NQK + wc * 64 + j * 16 + ec) =
                make_uint4(*(unsigned*)&h0, *(unsigned*)&h1,
                           *(unsigned*)&h2, *(unsigned*)&h3);
            __syncwarp();
        }
}

// ---------------------------------------------------------------------------
// Stage 2: neighbor scores from bf16 qk, one warp per (s,b).
// ---------------------------------------------------------------------------
__global__ __launch_bounds__(256) void scores(const float* __restrict__ bias)
{
    const int warp = threadIdx.x >> 5;
    const int lane = threadIdx.x & 31;
    const int m = blockIdx.x * 8 + warp;      // m = s*B + b
    const int s = m >> 5;
    const int b = m & 31;
    if (s >= S_ - 1) return;

    const __nv_bfloat16* r0 = g_qk + (size_t)m * NQK;
    const __nv_bfloat16* r1 = r0 + (size_t)B_ * NQK;

    uint2 uq0 = *(const uint2*)(r0 + lane * 4);
    uint2 uk0 = *(const uint2*)(r0 + P_ + lane * 4);
    uint2 uq1 = *(const uint2*)(r1 + lane * 4);
    uint2 uk1 = *(const uint2*)(r1 + P_ + lane * 4);
    float4 bq = *(const float4*)(bias + lane * 4);
    float4 bk = *(const float4*)(bias + P_ + lane * 4);

    float2 q0a = __bfloat1622float2(*(__nv_bfloat162*)&uq0.x);
    float2 q0b = __bfloat1622float2(*(__nv_bfloat162*)&uq0.y);
    float2 k0a = __bfloat1622float2(*(__nv_bfloat162*)&uk0.x);
    float2 k0b = __bfloat1622float2(*(__nv_bfloat162*)&uk0.y);
    float2 q1a = __bfloat1622float2(*(__nv_bfloat162*)&uq1.x);
    float2 q1b = __bfloat1622float2(*(__nv_bfloat162*)&uq1.y);
    float2 k1a = __bfloat1622float2(*(__nv_bfloat162*)&uk1.x);
    float2 k1b = __bfloat1622float2(*(__nv_bfloat162*)&uk1.y);

    float tf = (q0a.x + bq.x) * (k1a.x + bk.x)
             + (q0a.y + bq.y) * (k1a.y + bk.y)
             + (q0b.x + bq.z) * (k1b.x + bk.z)
             + (q0b.y + bq.w) * (k1b.y + bk.w);
    float tb = (q1a.x + bq.x) * (k0a.x + bk.x)
             + (q1a.y + bq.y) * (k0a.y + bk.y)
             + (q1b.x + bq.z) * (k0b.x + bk.z)
             + (q1b.y + bq.w) * (k0b.y + bk.w);

#pragma unroll
    for (int o = 16; o > 0; o >>= 1) {
        tf += __shfl_down_sync(0xffffffffu, tf, o);
        tb += __shfl_down_sync(0xffffffffu, tb, o);
    }
    if (lane == 0) {
        g_fwd[b * S_ + s] = tf * (1.0f / (float)E_);
        g_bwd[b * S_ + s] = tb * (1.0f / (float)E_);
    }
}

// ---------------------------------------------------------------------------
// Stage 3: softmax/roll/log + exclusive scan; stores f = exp(log_prob).
// ---------------------------------------------------------------------------
__global__ __launch_bounds__(1024) void rowscan(const float* __restrict__ prior,
                                                const int* __restrict__ mask,
                                                float* __restrict__ out_na)
{
    const int b = blockIdx.x;
    const int s = threadIdx.x;

    __shared__ float s_prob1[S_];
    __shared__ float s_warp[32];

    const int rm = mask[b * S_ + ((s + 1) & (S_ - 1))];

    float c0 = (s < S_ - 1) ? g_fwd[b * S_ + s] : -INFINITY;
    if (rm == 1) c0 = -INFINITY;
    float c1 = (s > 0) ? g_bwd[b * S_ + s - 1] : -INFINITY;

    float mx = fmaxf(c0, c1);
    float e0 = __expf(c0 - mx);
    float e1 = __expf(c1 - mx);
    float inv = 1.0f / (e0 + e1);
    float p0 = e0 * inv;
    float p1 = e1 * inv;

    s_prob1[s] = p1;
    __syncthreads();

    float shift = (s < S_ - 1) ? s_prob1[s + 1] : 0.0f;

    float pv = sqrtf(p0 * shift + 1e-6f);
    float pr = prior[b * S_ + s];
    float na = pr + (1.0f - pr) * pv;
    out_na[b * S_ + s] = na;

    float lp = logf(na);
    float fv = na;
    if (rm == 1) { lp = 0.0f; fv = 1.0f; }
    g_f[b * S_ + s] = fv;

    float v = lp;
    const unsigned lane = s & 31;
#pragma unroll
    for (int o = 1; o < 32; o <<= 1) {
        float n = __shfl_up_sync(0xffffffffu, v, o);
        if (lane >= (unsigned)o) v += n;
    }
    if (lane == 31) s_warp[s >> 5] = v;
    __syncthreads();
    if (s < 32) {
        float w = s_warp[s];
#pragma unroll
        for (int o = 1; o < 32; o <<= 1) {
            float n = __shfl_up_sync(0xffffffffu, w, o);
            if (s >= o) w += n;
        }
        s_warp[s] = w;
    }
    __syncthreads();
    float incl = v + ((s >= 32) ? s_warp[(s >> 5) - 1] : 0.0f);
    g_csp[b * S_ + s] = incl - lp;
}

// ---------------------------------------------------------------------------
// Stage 4: constituent[b][i][j]. 512 threads, 32 rows/block, min 3 blocks/SM.
// ---------------------------------------------------------------------------
constexpr int RPB = 32;

__global__ __launch_bounds__(512, 3) void outerk(float* __restrict__ out)
{
    const int b  = blockIdx.y;
    const int i0 = blockIdx.x * RPB;
    const int tid = threadIdx.x;

    __shared__ float sc[S_];
    __shared__ float sf[S_];
    if (tid < 256)
        ((float4*)sc)[tid] = ((const float4*)(g_csp + b * S_))[tid];
    else
        ((float4*)sf)[tid - 256] = ((const float4*)(g_f + b * S_))[tid - 256];
    __syncthreads();

    const int rsub = tid >> 7;            // 0..3
    const int j0 = (tid & 127) * 8;

    float4 f0 = *(const float4*)&sf[j0];
    float4 f1 = *(const float4*)&sf[j0 + 4];
    float4 c0 = *(const float4*)&sc[j0];
    float4 c1 = *(const float4*)&sc[j0 + 4];

#pragma unroll 4
    for (int sweep = 0; sweep < RPB / 4; sweep++) {
        const int i = i0 + sweep * 4 + rsub;
        const float ci = sc[i];

        float r[8];
        if (j0 + 7 < i) {
            float v = __expf(ci - c0.w);
            r[3] = v;
            v *= f0.z; r[2] = v;
            v *= f0.y; r[1] = v;
            v *= f0.x; r[0] = v;
            float w = __expf(ci - c1.w);
            r[7] = w;
            w *= f1.z; r[6] = w;
            w *= f1.y; r[5] = w;
            w *= f1.x; r[4] = w;
        } else if (j0 > i) {
            float v = __expf(c0.x - ci);
            r[0] = v;
            v *= f0.x; r[1] = v;
            v *= f0.y; r[2] = v;
            v *= f0.z; r[3] = v;
            float w = __expf(c1.x - ci);
            r[4] = w;
            w *= f1.x; r[5] = w;
            w *= f1.y; r[6] = w;
            w *= f1.z; r[7] = w;
        } else {
            const float cj[8] = {c0.x, c0.y, c0.z, c0.w, c1.x, c1.y, c1.z, c1.w};
#pragma unroll
            for (int l = 0; l < 8; l++) {
                int j = j0 + l;
                float d = (j > i) ? (cj[l] - ci) : (ci - cj[l]);
                r[l] = (j == i) ? 0.0f : __expf(d);
            }
        }

        float* dst = out + ((size_t)b * S_ + i) * S_ + j0;
        __stcs((float4*)dst,       make_float4(r[0], r[1], r[2], r[3]));
        __stcs((float4*)(dst + 4), make_float4(r[4], r[5], r[6], r[7]));
    }
}

// ---------------------------------------------------------------------------
extern "C" void kernel_launch(void* const* d_in, const int* in_sizes, int n_in,
                              void* d_out, int out_size)
{
    const float* ctx   = (const float*)d_in[0];
    const float* prior = (const float*)d_in[1];
    const int*   mask  = (const int*)d_in[2];
    const float* W     = (const float*)d_in[3];
    const float* bias  = (const float*)d_in[4];

    float* out_c  = (float*)d_out;
    float* out_na = (float*)d_out + (size_t)B_ * S_ * S_;

    conv_w<<<256, 256>>>(W);

    gemm_qk<<<(B_ * S_) / GBM, 256>>>(ctx);

    scores<<<(B_ * S_) / 8, 256>>>(bias);

    rowscan<<<B_, S_>>>(prior, mask, out_na);

    dim3 g4(S_ / RPB, B_);
    outerk<<<g4, 512>>>(out_c);
}

// round 13
// speedup vs baseline: 1.0877x; 1.0207x over previous
#include <cuda_runtime.h>
#include <cuda_bf16.h>
#include <mma.h>
#include <math.h>
#include <cstdint>

using namespace nvcuda;

constexpr int S_ = 1024;
constexpr int B_ = 32;
constexpr int E_ = 1024;
constexpr int P_ = 128;
constexpr int NQK = 2 * P_;   // 256

__device__ __nv_bfloat16 g_qk[(size_t)B_ * S_ * NQK];
__device__ __nv_bfloat16 g_Wb[(size_t)NQK * E_];
__device__ float g_fwd[B_ * S_];
__device__ float g_bwd[B_ * S_];

__device__ __forceinline__ uint32_t smem_u32(const void* p) {
    uint32_t a;
    asm("{ .reg .u64 t; cvta.to.shared.u64 t, %1; cvt.u32.u64 %0, t; }"
        : "=r"(a) : "l"(p));
    return a;
}
#define CP_ASYNC16(dst_u32, src_ptr) \
    asm volatile("cp.async.cg.shared.global [%0], [%1], 16;" \
                 :: "r"(dst_u32), "l"(src_ptr))
#define CP_COMMIT() asm volatile("cp.async.commit_group;" ::: "memory")
#define CP_WAIT1()  asm volatile("cp.async.wait_group 1;" ::: "memory")

// ---------------------------------------------------------------------------
// Stage 0: convert W (fp32 [256,1024]) to bf16 once.
// ---------------------------------------------------------------------------
__global__ __launch_bounds__(256) void conv_w(const float* __restrict__ W)
{
    int i = blockIdx.x * 256 + threadIdx.x;
    float4 v = ((const float4*)W)[i];
    __nv_bfloat162 p0 = __floats2bfloat162_rn(v.x, v.y);
    __nv_bfloat162 p1 = __floats2bfloat162_rn(v.z, v.w);
    *(uint2*)&g_Wb[(size_t)i * 4] = make_uint2(*(unsigned*)&p0, *(unsigned*)&p1);
}

// ---------------------------------------------------------------------------
// Stage 1: GEMM qk = ctx @ W^T. (round-12 config; near legacy-HMMA pipe rate)
// ---------------------------------------------------------------------------
constexpr int GBM = 64;
constexpr int GBK = 16;
constexpr int GLD = 24;
constexpr int A_ST = GBM * GLD;
constexpr int B_ST = NQK * GLD;
constexpr int NSLAB = E_ / GBK;   // 64

__global__ __launch_bounds__(256, 2) void gemm_qk(const float* __restrict__ ctx)
{
    __shared__ __nv_bfloat16 As[2][GBM][GLD];
    __shared__ __nv_bfloat16 Bs[3][NQK][GLD];
    __shared__ float epi[8][16 * 24];

    const int m0 = blockIdx.x * GBM;
    const int tid = threadIdx.x;
    const int warp = tid >> 5;
    const int lane = tid & 31;
    const int wr = warp & 1;
    const int wc = warp >> 1;

    const int lr = tid >> 2;
    const int lc = (tid & 3) * 4;

    const int br0 = tid >> 1;
    const int bh0 = tid & 1;
    const uint32_t bs_base = smem_u32(&Bs[0][0][0]);

    wmma::fragment<wmma::accumulator, 16, 16, 16, float> acc[2][4];
#pragma unroll
    for (int i = 0; i < 2; i++)
#pragma unroll
        for (int j = 0; j < 4; j++)
            wmma::fill_fragment(acc[i][j], 0.0f);

    auto cpB = [&](int t, int buf) {
#pragma unroll
        for (int it = 0; it < 2; it++) {
            int row = br0 + it * 128;
            const __nv_bfloat16* src = g_Wb + (size_t)row * E_ + t * GBK + bh0 * 8;
            uint32_t dst = bs_base + buf * (B_ST * 2) + row * 48 + bh0 * 16;
            CP_ASYNC16(dst, src);
        }
    };

    float4 ra;
    auto ldgA = [&](int t) {
        ra = *(const float4*)(ctx + (size_t)(m0 + lr) * E_ + t * GBK + lc);
    };
    auto stsA = [&](int buf) {
        __nv_bfloat162 a01 = __floats2bfloat162_rn(ra.x, ra.y);
        __nv_bfloat162 a23 = __floats2bfloat162_rn(ra.z, ra.w);
        *(uint2*)(uintptr_t)(&As[buf][lr][lc]) =
            make_uint2(*(unsigned*)&a01, *(unsigned*)&a23);
    };

    cpB(0, 0); CP_COMMIT();
    cpB(1, 1); CP_COMMIT();
    ldgA(0);
    stsA(0);
    ldgA(1);
    CP_WAIT1();
    __syncthreads();

    for (int t = 0; t < NSLAB; t++) {
        if (t + 2 < NSLAB) cpB(t + 2, (t + 2) % 3);
        CP_COMMIT();

        const int ab = t & 1;
        const int bb = t % 3;
        wmma::fragment<wmma::matrix_a, 16, 16, 16, __nv_bfloat16, wmma::row_major> af[2];
        wmma::fragment<wmma::matrix_b, 16, 16, 16, __nv_bfloat16, wmma::col_major> bf[4];
#pragma unroll
        for (int i = 0; i < 2; i++)
            wmma::load_matrix_sync(af[i], &As[ab][wr * 32 + i * 16][0], GLD);
#pragma unroll
        for (int j = 0; j < 4; j++)
            wmma::load_matrix_sync(bf[j], &Bs[bb][wc * 64 + j * 16][0], GLD);
#pragma unroll
        for (int i = 0; i < 2; i++)
#pragma unroll
            for (int j = 0; j < 4; j++)
                wmma::mma_sync(acc[i][j], af[i], bf[j], acc[i][j]);

        if (t + 1 < NSLAB) {
            stsA((t + 1) & 1);
            if (t + 2 < NSLAB) ldgA(t + 2);
            CP_WAIT1();
            __syncthreads();
        }
    }

    float* ebuf = epi[warp];
    const int er = lane >> 1;
    const int ec = (lane & 1) * 8;
#pragma unroll
    for (int i = 0; i < 2; i++)
#pragma unroll
        for (int j = 0; j < 4; j++) {
            wmma::store_matrix_sync(ebuf, acc[i][j], 24, wmma::mem_row_major);
            __syncwarp();
            const float* p = ebuf + er * 24 + ec;
            __nv_bfloat162 h0 = __floats2bfloat162_rn(p[0], p[1]);
            __nv_bfloat162 h1 = __floats2bfloat162_rn(p[2], p[3]);
            __nv_bfloat162 h2 = __floats2bfloat162_rn(p[4], p[5]);
            __nv_bfloat162 h3 = __floats2bfloat162_rn(p[6], p[7]);
            size_t row = m0 + wr * 32 + i * 16 + er;
            *(uint4*)(g_qk + row * NQK + wc * 64 + j * 16 + ec) =
                make_uint4(*(unsigned*)&h0, *(unsigned*)&h1,
                           *(unsigned*)&h2, *(unsigned*)&h3);
            __syncwarp();
        }
}

// ---------------------------------------------------------------------------
// Stage 2: neighbor scores from bf16 qk, one warp per (s,b).
// ---------------------------------------------------------------------------
__global__ __launch_bounds__(256) void scores(const float* __restrict__ bias)
{
    const int warp = threadIdx.x >> 5;
    const int lane = threadIdx.x & 31;
    const int m = blockIdx.x * 8 + warp;
    const int s = m >> 5;
    const int b = m & 31;
    if (s >= S_ - 1) return;

    const __nv_bfloat16* r0 = g_qk + (size_t)m * NQK;
    const __nv_bfloat16* r1 = r0 + (size_t)B_ * NQK;

    uint2 uq0 = *(const uint2*)(r0 + lane * 4);
    uint2 uk0 = *(const uint2*)(r0 + P_ + lane * 4);
    uint2 uq1 = *(const uint2*)(r1 + lane * 4);
    uint2 uk1 = *(const uint2*)(r1 + P_ + lane * 4);
    float4 bq = *(const float4*)(bias + lane * 4);
    float4 bk = *(const float4*)(bias + P_ + lane * 4);

    float2 q0a = __bfloat1622float2(*(__nv_bfloat162*)&uq0.x);
    float2 q0b = __bfloat1622float2(*(__nv_bfloat162*)&uq0.y);
    float2 k0a = __bfloat1622float2(*(__nv_bfloat162*)&uk0.x);
    float2 k0b = __bfloat1622float2(*(__nv_bfloat162*)&uk0.y);
    float2 q1a = __bfloat1622float2(*(__nv_bfloat162*)&uq1.x);
    float2 q1b = __bfloat1622float2(*(__nv_bfloat162*)&uq1.y);
    float2 k1a = __bfloat1622float2(*(__nv_bfloat162*)&uk1.x);
    float2 k1b = __bfloat1622float2(*(__nv_bfloat162*)&uk1.y);

    float tf = (q0a.x + bq.x) * (k1a.x + bk.x)
             + (q0a.y + bq.y) * (k1a.y + bk.y)
             + (q0b.x + bq.z) * (k1b.x + bk.z)
             + (q0b.y + bq.w) * (k1b.y + bk.w);
    float tb = (q1a.x + bq.x) * (k0a.x + bk.x)
             + (q1a.y + bq.y) * (k0a.y + bk.y)
             + (q1b.x + bq.z) * (k0b.x + bk.z)
             + (q1b.y + bq.w) * (k0b.y + bk.w);

#pragma unroll
    for (int o = 16; o > 0; o >>= 1) {
        tf += __shfl_down_sync(0xffffffffu, tf, o);
        tb += __shfl_down_sync(0xffffffffu, tb, o);
    }
    if (lane == 0) {
        g_fwd[b * S_ + s] = tf * (1.0f / (float)E_);
        g_bwd[b * S_ + s] = tb * (1.0f / (float)E_);
    }
}

// ---------------------------------------------------------------------------
// Stage 3+4 fused: per-block replicated softmax/log/scan (in smem), then
// outer product. 1024 threads, RPB=64 rows/block, grid (16, 32).
// ---------------------------------------------------------------------------
constexpr int RPB = 64;

__global__ __launch_bounds__(1024, 2) void outerk(
    const float* __restrict__ prior, const int* __restrict__ mask,
    float* __restrict__ out, float* __restrict__ out_na)
{
    const int b  = blockIdx.y;
    const int i0 = blockIdx.x * RPB;
    const int tid = threadIdx.x;
    const int s = tid;

    __shared__ float sc[S_];
    __shared__ float sf[S_];
    __shared__ float s_warp[32];

    // ---- scan phase (replicated across i-blocks) ----
    const int rm = mask[b * S_ + ((s + 1) & (S_ - 1))];
    float c0v = (s < S_ - 1) ? g_fwd[b * S_ + s] : -INFINITY;
    if (rm == 1) c0v = -INFINITY;
    float c1v = (s > 0) ? g_bwd[b * S_ + s - 1] : -INFINITY;

    float mx = fmaxf(c0v, c1v);
    float e0 = __expf(c0v - mx);
    float e1 = __expf(c1v - mx);
    float inv = 1.0f / (e0 + e1);
    float p0 = e0 * inv;
    float p1 = e1 * inv;

    sc[s] = p1;                       // stash prob1 temporarily
    __syncthreads();
    float shift = (s < S_ - 1) ? sc[s + 1] : 0.0f;   // wrap value is 0
    __syncthreads();                  // before sc is overwritten

    float pv = sqrtf(p0 * shift + 1e-6f);
    float pr = prior[b * S_ + s];
    float na = pr + (1.0f - pr) * pv;
    if (blockIdx.x == 0) out_na[b * S_ + s] = na;

    float lp = logf(na);
    float fv = na;
    if (rm == 1) { lp = 0.0f; fv = 1.0f; }
    sf[s] = fv;

    float v = lp;
    const unsigned lane = s & 31;
#pragma unroll
    for (int o = 1; o < 32; o <<= 1) {
        float n = __shfl_up_sync(0xffffffffu, v, o);
        if (lane >= (unsigned)o) v += n;
    }
    if (lane == 31) s_warp[s >> 5] = v;
    __syncthreads();
    if (s < 32) {
        float w = s_warp[s];
#pragma unroll
        for (int o = 1; o < 32; o <<= 1) {
            float n = __shfl_up_sync(0xffffffffu, w, o);
            if (s >= o) w += n;
        }
        s_warp[s] = w;
    }
    __syncthreads();
    float incl = v + ((s >= 32) ? s_warp[(s >> 5) - 1] : 0.0f);
    sc[s] = incl - lp;                // exclusive prefix sum
    __syncthreads();

    // ---- outer product phase: 8 rows in flight ----
    const int rsub = tid >> 7;            // 0..7
    const int j0 = (tid & 127) * 8;

    float4 f0 = *(const float4*)&sf[j0];
    float4 f1 = *(const float4*)&sf[j0 + 4];
    float4 c0 = *(const float4*)&sc[j0];
    float4 c1 = *(const float4*)&sc[j0 + 4];

#pragma unroll 4
    for (int sweep = 0; sweep < RPB / 8; sweep++) {
        const int i = i0 + sweep * 8 + rsub;
        const float ci = sc[i];

        float r[8];
        if (j0 + 7 < i) {
            float v2 = __expf(ci - c0.w);
            r[3] = v2;
            v2 *= f0.z; r[2] = v2;
            v2 *= f0.y; r[1] = v2;
            v2 *= f0.x; r[0] = v2;
            float w2 = __expf(ci - c1.w);
            r[7] = w2;
            w2 *= f1.z; r[6] = w2;
            w2 *= f1.y; r[5] = w2;
            w2 *= f1.x; r[4] = w2;
        } else if (j0 > i) {
            float v2 = __expf(c0.x - ci);
            r[0] = v2;
            v2 *= f0.x; r[1] = v2;
            v2 *= f0.y; r[2] = v2;
            v2 *= f0.z; r[3] = v2;
            float w2 = __expf(c1.x - ci);
            r[4] = w2;
            w2 *= f1.x; r[5] = w2;
            w2 *= f1.y; r[6] = w2;
            w2 *= f1.z; r[7] = w2;
        } else {
            const float cj[8] = {c0.x, c0.y, c0.z, c0.w, c1.x, c1.y, c1.z, c1.w};
#pragma unroll
            for (int l = 0; l < 8; l++) {
                int j = j0 + l;
                float d = (j > i) ? (cj[l] - ci) : (ci - cj[l]);
                r[l] = (j == i) ? 0.0f : __expf(d);
            }
        }

        float* dst = out + ((size_t)b * S_ + i) * S_ + j0;
        __stcs((float4*)dst,       make_float4(r[0], r[1], r[2], r[3]));
        __stcs((float4*)(dst + 4), make_float4(r[4], r[5], r[6], r[7]));
    }
}

// ---------------------------------------------------------------------------
extern "C" void kernel_launch(void* const* d_in, const int* in_sizes, int n_in,
                              void* d_out, int out_size)
{
    const float* ctx   = (const float*)d_in[0];
    const float* prior = (const float*)d_in[1];
    const int*   mask  = (const int*)d_in[2];
    const float* W     = (const float*)d_in[3];
    const float* bias  = (const float*)d_in[4];

    float* out_c  = (float*)d_out;
    float* out_na = (float*)d_out + (size_t)B_ * S_ * S_;

    conv_w<<<256, 256>>>(W);

    gemm_qk<<<(B_ * S_) / GBM, 256>>>(ctx);

    scores<<<(B_ * S_) / 8, 256>>>(bias);

    dim3 g4(S_ / RPB, B_);
    outerk<<<g4, 1024>>>(prior, mask, out_c, out_na);
}

// round 14
// speedup vs baseline: 1.3276x; 1.2206x over previous
#include <cuda_runtime.h>
#include <cuda_fp16.h>
#include <mma.h>
#include <math.h>
#include <cstdint>

using namespace nvcuda;

constexpr int S_ = 1024;
constexpr int B_ = 32;
constexpr int E_ = 1024;
constexpr int P_ = 128;
constexpr int NQK = 2 * P_;   // 256

__device__ __half g_qk[(size_t)B_ * S_ * NQK];
__device__ __half g_Wb[(size_t)NQK * E_];
__device__ float g_fwd[B_ * S_];
__device__ float g_bwd[B_ * S_];

__device__ __forceinline__ uint32_t smem_u32(const void* p) {
    uint32_t a;
    asm("{ .reg .u64 t; cvta.to.shared.u64 t, %1; cvt.u32.u64 %0, t; }"
        : "=r"(a) : "l"(p));
    return a;
}
#define CP_ASYNC16(dst_u32, src_ptr) \
    asm volatile("cp.async.cg.shared.global [%0], [%1], 16;" \
                 :: "r"(dst_u32), "l"(src_ptr))
#define CP_COMMIT() asm volatile("cp.async.commit_group;" ::: "memory")
#define CP_WAIT1()  asm volatile("cp.async.wait_group 1;" ::: "memory")

// ---------------------------------------------------------------------------
// Stage 0: convert W (fp32 [256,1024]) to fp16 once.
// ---------------------------------------------------------------------------
__global__ __launch_bounds__(256) void conv_w(const float* __restrict__ W)
{
    int i = blockIdx.x * 256 + threadIdx.x;
    float4 v = ((const float4*)W)[i];
    __half2 p0 = __float22half2_rn(make_float2(v.x, v.y));
    __half2 p1 = __float22half2_rn(make_float2(v.z, v.w));
    *(uint2*)&g_Wb[(size_t)i * 4] = make_uint2(*(unsigned*)&p0, *(unsigned*)&p1);
}

// ---------------------------------------------------------------------------
// Stage 1: GEMM qk = ctx @ W^T. M=32768, N=256, K=1024.
// fp16 wmma m16n16k16 with FP16 ACCUMULATORS (2x legacy HMMA rate).
// BM=64, BN=256, BK=16; 256 threads (8 warps 2x4), warp tile 32x64.
// B: 3-stage cp.async from g_Wb. A: 2-stage LDG->cvt->STS.
// ---------------------------------------------------------------------------
constexpr int GBM = 64;
constexpr int GBK = 16;
constexpr int GLD = 24;                 // fp16 per smem row (48B)
constexpr int A_ST = GBM * GLD;
constexpr int B_ST = NQK * GLD;
constexpr int NSLAB = E_ / GBK;         // 64

__global__ __launch_bounds__(256, 2) void gemm_qk(const float* __restrict__ ctx)
{
    __shared__ __half As[2][GBM][GLD];
    __shared__ __half Bs[3][NQK][GLD];

    const int m0 = blockIdx.x * GBM;
    const int tid = threadIdx.x;
    const int warp = tid >> 5;
    const int wr = warp & 1;
    const int wc = warp >> 1;

    const int lr = tid >> 2;          // A row 0..63
    const int lc = (tid & 3) * 4;     // A col start

    const int br0 = tid >> 1;         // B cp.async row base (0..127)
    const int bh0 = tid & 1;
    const uint32_t bs_base = smem_u32(&Bs[0][0][0]);

    wmma::fragment<wmma::accumulator, 16, 16, 16, __half> acc[2][4];
#pragma unroll
    for (int i = 0; i < 2; i++)
#pragma unroll
        for (int j = 0; j < 4; j++)
            wmma::fill_fragment(acc[i][j], __float2half(0.0f));

    auto cpB = [&](int t, int buf) {
#pragma unroll
        for (int it = 0; it < 2; it++) {
            int row = br0 + it * 128;
            const __half* src = g_Wb + (size_t)row * E_ + t * GBK + bh0 * 8;
            uint32_t dst = bs_base + buf * (B_ST * 2) + row * 48 + bh0 * 16;
            CP_ASYNC16(dst, src);
        }
    };

    float4 ra;
    auto ldgA = [&](int t) {
        ra = *(const float4*)(ctx + (size_t)(m0 + lr) * E_ + t * GBK + lc);
    };
    auto stsA = [&](int buf) {
        __half2 a01 = __float22half2_rn(make_float2(ra.x, ra.y));
        __half2 a23 = __float22half2_rn(make_float2(ra.z, ra.w));
        *(uint2*)(uintptr_t)(&As[buf][lr][lc]) =
            make_uint2(*(unsigned*)&a01, *(unsigned*)&a23);
    };

    // prologue
    cpB(0, 0); CP_COMMIT();
    cpB(1, 1); CP_COMMIT();
    ldgA(0);
    stsA(0);
    ldgA(1);
    CP_WAIT1();
    __syncthreads();

    for (int t = 0; t < NSLAB; t++) {
        if (t + 2 < NSLAB) cpB(t + 2, (t + 2) % 3);
        CP_COMMIT();

        const int ab = t & 1;
        const int bb = t % 3;
        wmma::fragment<wmma::matrix_a, 16, 16, 16, __half, wmma::row_major> af[2];
        wmma::fragment<wmma::matrix_b, 16, 16, 16, __half, wmma::col_major> bf[4];
#pragma unroll
        for (int i = 0; i < 2; i++)
            wmma::load_matrix_sync(af[i], &As[ab][wr * 32 + i * 16][0], GLD);
#pragma unroll
        for (int j = 0; j < 4; j++)
            wmma::load_matrix_sync(bf[j], &Bs[bb][wc * 64 + j * 16][0], GLD);
#pragma unroll
        for (int i = 0; i < 2; i++)
#pragma unroll
            for (int j = 0; j < 4; j++)
                wmma::mma_sync(acc[i][j], af[i], bf[j], acc[i][j]);

        if (t + 1 < NSLAB) {
            stsA((t + 1) & 1);
            if (t + 2 < NSLAB) ldgA(t + 2);
            CP_WAIT1();
            __syncthreads();
        }
    }

    // epilogue: direct half store of fragments
#pragma unroll
    for (int i = 0; i < 2; i++)
#pragma unroll
        for (int j = 0; j < 4; j++) {
            __half* dst = g_qk + (size_t)(m0 + wr * 32 + i * 16) * NQK
                               + wc * 64 + j * 16;
            wmma::store_matrix_sync(dst, acc[i][j], NQK, wmma::mem_row_major);
        }
}

// ---------------------------------------------------------------------------
// Stage 2: neighbor scores from fp16 qk, one warp per (s,b).
// ---------------------------------------------------------------------------
__global__ __launch_bounds__(256) void scores(const float* __restrict__ bias)
{
    const int warp = threadIdx.x >> 5;
    const int lane = threadIdx.x & 31;
    const int m = blockIdx.x * 8 + warp;
    const int s = m >> 5;
    const int b = m & 31;
    if (s >= S_ - 1) return;

    const __half* r0 = g_qk + (size_t)m * NQK;
    const __half* r1 = r0 + (size_t)B_ * NQK;

    uint2 uq0 = *(const uint2*)(r0 + lane * 4);
    uint2 uk0 = *(const uint2*)(r0 + P_ + lane * 4);
    uint2 uq1 = *(const uint2*)(r1 + lane * 4);
    uint2 uk1 = *(const uint2*)(r1 + P_ + lane * 4);
    float4 bq = *(const float4*)(bias + lane * 4);
    float4 bk = *(const float4*)(bias + P_ + lane * 4);

    float2 q0a = __half22float2(*(__half2*)&uq0.x);
    float2 q0b = __half22float2(*(__half2*)&uq0.y);
    float2 k0a = __half22float2(*(__half2*)&uk0.x);
    float2 k0b = __half22float2(*(__half2*)&uk0.y);
    float2 q1a = __half22float2(*(__half2*)&uq1.x);
    float2 q1b = __half22float2(*(__half2*)&uq1.y);
    float2 k1a = __half22float2(*(__half2*)&uk1.x);
    float2 k1b = __half22float2(*(__half2*)&uk1.y);

    float tf = (q0a.x + bq.x) * (k1a.x + bk.x)
             + (q0a.y + bq.y) * (k1a.y + bk.y)
             + (q0b.x + bq.z) * (k1b.x + bk.z)
             + (q0b.y + bq.w) * (k1b.y + bk.w);
    float tb = (q1a.x + bq.x) * (k0a.x + bk.x)
             + (q1a.y + bq.y) * (k0a.y + bk.y)
             + (q1b.x + bq.z) * (k0b.x + bk.z)
             + (q1b.y + bq.w) * (k0b.y + bk.w);

#pragma unroll
    for (int o = 16; o > 0; o >>= 1) {
        tf += __shfl_down_sync(0xffffffffu, tf, o);
        tb += __shfl_down_sync(0xffffffffu, tb, o);
    }
    if (lane == 0) {
        g_fwd[b * S_ + s] = tf * (1.0f / (float)E_);
        g_bwd[b * S_ + s] = tb * (1.0f / (float)E_);
    }
}

// ---------------------------------------------------------------------------
// Stage 3+4 fused: per-block replicated softmax/log/scan, then outer product.
// 1024 threads, RPB=64 rows/block, grid (16, 32).
// ---------------------------------------------------------------------------
constexpr int RPB = 64;

__global__ __launch_bounds__(1024, 2) void outerk(
    const float* __restrict__ prior, const int* __restrict__ mask,
    float* __restrict__ out, float* __restrict__ out_na)
{
    const int b  = blockIdx.y;
    const int i0 = blockIdx.x * RPB;
    const int tid = threadIdx.x;
    const int s = tid;

    __shared__ float sc[S_];
    __shared__ float sf[S_];
    __shared__ float s_warp[32];

    const int rm = mask[b * S_ + ((s + 1) & (S_ - 1))];
    float c0v = (s < S_ - 1) ? g_fwd[b * S_ + s] : -INFINITY;
    if (rm == 1) c0v = -INFINITY;
    float c1v = (s > 0) ? g_bwd[b * S_ + s - 1] : -INFINITY;

    float mx = fmaxf(c0v, c1v);
    float e0 = __expf(c0v - mx);
    float e1 = __expf(c1v - mx);
    float inv = 1.0f / (e0 + e1);
    float p0 = e0 * inv;
    float p1 = e1 * inv;

    sc[s] = p1;
    __syncthreads();
    float shift = (s < S_ - 1) ? sc[s + 1] : 0.0f;
    __syncthreads();

    float pv = sqrtf(p0 * shift + 1e-6f);
    float pr = prior[b * S_ + s];
    float na = pr + (1.0f - pr) * pv;
    if (blockIdx.x == 0) out_na[b * S_ + s] = na;

    float lp = logf(na);
    float fv = na;
    if (rm == 1) { lp = 0.0f; fv = 1.0f; }
    sf[s] = fv;

    float v = lp;
    const unsigned lane = s & 31;
#pragma unroll
    for (int o = 1; o < 32; o <<= 1) {
        float n = __shfl_up_sync(0xffffffffu, v, o);
        if (lane >= (unsigned)o) v += n;
    }
    if (lane == 31) s_warp[s >> 5] = v;
    __syncthreads();
    if (s < 32) {
        float w = s_warp[s];
#pragma unroll
        for (int o = 1; o < 32; o <<= 1) {
            float n = __shfl_up_sync(0xffffffffu, w, o);
            if (s >= o) w += n;
        }
        s_warp[s] = w;
    }
    __syncthreads();
    float incl = v + ((s >= 32) ? s_warp[(s >> 5) - 1] : 0.0f);
    sc[s] = incl - lp;
    __syncthreads();

    const int rsub = tid >> 7;            // 0..7
    const int j0 = (tid & 127) * 8;

    float4 f0 = *(const float4*)&sf[j0];
    float4 f1 = *(const float4*)&sf[j0 + 4];
    float4 c0 = *(const float4*)&sc[j0];
    float4 c1 = *(const float4*)&sc[j0 + 4];

#pragma unroll 4
    for (int sweep = 0; sweep < RPB / 8; sweep++) {
        const int i = i0 + sweep * 8 + rsub;
        const float ci = sc[i];

        float r[8];
        if (j0 + 7 < i) {
            float v2 = __expf(ci - c0.w);
            r[3] = v2;
            v2 *= f0.z; r[2] = v2;
            v2 *= f0.y; r[1] = v2;
            v2 *= f0.x; r[0] = v2;
            float w2 = __expf(ci - c1.w);
            r[7] = w2;
            w2 *= f1.z; r[6] = w2;
            w2 *= f1.y; r[5] = w2;
            w2 *= f1.x; r[4] = w2;
        } else if (j0 > i) {
            float v2 = __expf(c0.x - ci);
            r[0] = v2;
            v2 *= f0.x; r[1] = v2;
            v2 *= f0.y; r[2] = v2;
            v2 *= f0.z; r[3] = v2;
            float w2 = __expf(c1.x - ci);
            r[4] = w2;
            w2 *= f1.x; r[5] = w2;
            w2 *= f1.y; r[6] = w2;
            w2 *= f1.z; r[7] = w2;
        } else {
            const float cj[8] = {c0.x, c0.y, c0.z, c0.w, c1.x, c1.y, c1.z, c1.w};
#pragma unroll
            for (int l = 0; l < 8; l++) {
                int j = j0 + l;
                float d = (j > i) ? (cj[l] - ci) : (ci - cj[l]);
                r[l] = (j == i) ? 0.0f : __expf(d);
            }
        }

        float* dst = out + ((size_t)b * S_ + i) * S_ + j0;
        __stcs((float4*)dst,       make_float4(r[0], r[1], r[2], r[3]));
        __stcs((float4*)(dst + 4), make_float4(r[4], r[5], r[6], r[7]));
    }
}

// ---------------------------------------------------------------------------
extern "C" void kernel_launch(void* const* d_in, const int* in_sizes, int n_in,
                              void* d_out, int out_size)
{
    const float* ctx   = (const float*)d_in[0];
    const float* prior = (const float*)d_in[1];
    const int*   mask  = (const int*)d_in[2];
    const float* W     = (const float*)d_in[3];
    const float* bias  = (const float*)d_in[4];

    float* out_c  = (float*)d_out;
    float* out_na = (float*)d_out + (size_t)B_ * S_ * S_;

    conv_w<<<256, 256>>>(W);

    gemm_qk<<<(B_ * S_) / GBM, 256>>>(ctx);

    scores<<<(B_ * S_) / 8, 256>>>(bias);

    dim3 g4(S_ / RPB, B_);
    outerk<<<g4, 1024>>>(prior, mask, out_c, out_na);
}